// round 16
// baseline (speedup 1.0000x reference)
#include <cuda_runtime.h>
#include <cuda_fp16.h>
#include <math.h>
#include <stdint.h>

// ---------------- problem constants ----------------
#define BB   4
#define TT   256
#define NT   (BB*TT)        // 1024 tokens
#define EE   768
#define E3   (3*EE)         // 2304
#define HH   12
#define DD   64
#define LL   6
#define VV   100277
#define VPAD 100352         // VV padded to multiple of 256
#define FF   (4*EE)         // 3072
#define KSPL 4              // split-K factor

// ---------------- scratch (device globals; no allocations) ----------------
__device__ float  g_x    [NT*EE];
__device__ __half g_h    [NT*EE];
__device__ __half g_qkv  [NT*E3];
__device__ __half g_o    [NT*EE];
__device__ __half g_mlp  [NT*FF];
__device__ float  g_part [KSPL*NT*EE];
__device__ float  g_pl   [2*512*HH];
__device__ float  g_expsum[NT];
__device__ __half g_wqkvT[(long)LL*E3*EE];
__device__ __half g_woT  [(long)LL*EE*EE];
__device__ __half g_w1T  [(long)LL*FF*EE];
__device__ __half g_w2T  [(long)LL*EE*FF];
__device__ __half g_wlmT [(long)VPAD*EE];

// ---------------- small helpers ----------------
__device__ __forceinline__ uint32_t smem_u32(const void* p) {
    uint32_t a;
    asm("{ .reg .u64 t; cvta.to.shared.u64 t, %1; cvt.u32.u64 %0, t; }" : "=r"(a) : "l"(p));
    return a;
}
#define CP_ASYNC16(dst, src) \
    asm volatile("cp.async.cg.shared.global [%0], [%1], 16;" :: "r"(dst), "l"(src))
#define CP_COMMIT() asm volatile("cp.async.commit_group;" ::: "memory")
#define CP_WAIT1()  asm volatile("cp.async.wait_group 1;" ::: "memory")
#define CP_WAIT0()  asm volatile("cp.async.wait_group 0;" ::: "memory")

#define LDMX4(r0, r1, r2, r3, addr) \
    asm volatile("ldmatrix.sync.aligned.m8n8.x4.shared.b16 {%0,%1,%2,%3}, [%4];" \
        : "=r"(r0), "=r"(r1), "=r"(r2), "=r"(r3) : "r"(addr))

__device__ __forceinline__ void mma_f16(float* c, const uint32_t* a,
                                        uint32_t b0, uint32_t b1) {
    asm volatile(
        "mma.sync.aligned.m16n8k16.row.col.f32.f16.f16.f32 "
        "{%0,%1,%2,%3}, {%4,%5,%6,%7}, {%8,%9}, {%0,%1,%2,%3};"
        : "+f"(c[0]), "+f"(c[1]), "+f"(c[2]), "+f"(c[3])
        : "r"(a[0]), "r"(a[1]), "r"(a[2]), "r"(a[3]), "r"(b0), "r"(b1));
}

// FMA-pipe exp: exp(x) = 2^(x*log2e), degree-6 poly, ~1e-8 rel.
__device__ __forceinline__ float exp_poly(float x) {
    float t = x * 1.4426950408889634f;
    float fi = floorf(t);
    float f = t - fi;
    float p = 1.535336188319500e-4f;
    p = p * f + 1.339887440266574e-3f;
    p = p * f + 9.618437357674640e-3f;
    p = p * f + 5.550332471162809e-2f;
    p = p * f + 2.402264791363012e-1f;
    p = p * f + 6.931472028550421e-1f;
    p = p * f + 1.0f;
    return p * __int_as_float(((int)fi + 127) << 23);
}

// ---------------- transpose + fp32->fp16 (small weights) ----------------
__global__ void tr_half(const float* __restrict__ src, __half* __restrict__ dst,
                        int K, int N, int zmod,
                        long zsl, long zsh, long zdl, long zdh)
{
    int z = blockIdx.z;
    int l = z / zmod, hh = z % zmod;
    src += (long)l*zsl + (long)hh*zsh;
    dst += (long)l*zdl + (long)hh*zdh;
    __shared__ float t[32][33];
    int n0 = blockIdx.x*32, k0 = blockIdx.y*32;
    #pragma unroll
    for (int j = 0; j < 4; j++) {
        int k = k0 + threadIdx.y + j*8, n = n0 + threadIdx.x;
        t[threadIdx.y + j*8][threadIdx.x] = src[(long)k*N + n];
    }
    __syncthreads();
    #pragma unroll
    for (int j = 0; j < 4; j++) {
        int n = n0 + threadIdx.y + j*8, k = k0 + threadIdx.x;
        dst[(long)n*K + k] = __float2half_rn(t[threadIdx.x][threadIdx.y + j*8]);
    }
}

// ---------------- fast lm_w transpose: [E][VV] fp32 -> [VPAD][E] half ----------------
__global__ void __launch_bounds__(256)
tr_lm(const float* __restrict__ src, __half* __restrict__ dst)
{
    __shared__ float t[64][33];
    int n0 = blockIdx.x*32, k0 = blockIdx.y*64;
    int tx = threadIdx.x & 31, ty = threadIdx.x >> 5;
    #pragma unroll
    for (int j = 0; j < 8; j++) {
        int k = ty + j*8;
        int n = n0 + tx;
        t[k][tx] = (n < VV) ? src[(long)(k0 + k)*VV + n] : 0.f;
    }
    __syncthreads();
    #pragma unroll
    for (int i = 0; i < 4; i++) {
        int idx = threadIdx.x + i*256;
        int n = idx >> 5;
        int c = idx & 31;
        __half2 hv = __floats2half2_rn(t[c*2][n], t[c*2+1][n]);
        *((__half2*)(dst + (long)(n0 + n)*EE + k0 + c*2)) = hv;
    }
}

__global__ void zero_kernel(float* p) { p[threadIdx.x] = 0.f; }

// ---------------- shared LN tail: warp-shuffle reduce of (s, s2) ----------------
__device__ __forceinline__ void ln_stats(float s, float s2, int tid,
                                         float& mu, float& inv)
{
    #pragma unroll
    for (int off = 16; off > 0; off >>= 1) {
        s  += __shfl_xor_sync(0xFFFFFFFFu, s,  off);
        s2 += __shfl_xor_sync(0xFFFFFFFFu, s2, off);
    }
    __shared__ float ws[8], ws2[8], smu, sinv;
    if ((tid & 31) == 0) { ws[tid >> 5] = s; ws2[tid >> 5] = s2; }
    __syncthreads();
    if (tid == 0) {
        float S = 0.f, S2 = 0.f;
        #pragma unroll
        for (int i = 0; i < 8; i++) { S += ws[i]; S2 += ws2[i]; }
        float m = S * (1.0f/EE);
        smu = m;
        sinv = rsqrtf(S2 * (1.0f/EE) - m*m + 1e-5f);
    }
    __syncthreads();
    mu = smu; inv = sinv;
}

// ---------------- fused embed + LN1(layer 0): h half ----------------
__global__ void embed_ln_kernel(const int* __restrict__ idx,
                                const float* __restrict__ tok,
                                const float* __restrict__ pos,
                                const float* __restrict__ g,
                                const float* __restrict__ b,
                                float* __restrict__ x,
                                __half* __restrict__ h)
{
    int row = blockIdx.x;
    int t   = row % TT;
    int token = idx[row];
    const float* tr = tok + (long)token * EE;
    const float* pr = pos + (long)t * EE;
    int tid = threadIdx.x;
    float vals[3];
    float s = 0.f, s2 = 0.f;
    #pragma unroll
    for (int i = 0; i < 3; i++) {
        int col = tid + i*256;
        float v = tr[col] + pr[col];
        x[(long)row*EE + col] = v;
        vals[i] = v; s += v; s2 += v*v;
    }
    float mu, inv;
    ln_stats(s, s2, tid, mu, inv);
    #pragma unroll
    for (int i = 0; i < 3; i++) {
        int col = tid + i*256;
        h[(long)row*EE + col] = __float2half_rn((vals[i] - mu) * inv * g[col] + b[col]);
    }
}

// ---------------- fused: x += sum(part)+bias; h = LN(x) half ----------------
__global__ void reduce_ln_kernel(const float* __restrict__ part,
                                 const float* __restrict__ bias,
                                 float* __restrict__ x,
                                 const float* __restrict__ g,
                                 const float* __restrict__ b,
                                 __half* __restrict__ h)
{
    int row = blockIdx.x;
    int tid = threadIdx.x;
    float vals[3];
    float s = 0.f, s2 = 0.f;
    #pragma unroll
    for (int i = 0; i < 3; i++) {
        int col = tid + i*256;
        float v = x[(long)row*EE + col] + bias[col];
        #pragma unroll
        for (int z = 0; z < KSPL; z++)
            v += part[((long)z*NT + row)*EE + col];
        x[(long)row*EE + col] = v;
        vals[i] = v; s += v; s2 += v*v;
    }
    float mu, inv;
    ln_stats(s, s2, tid, mu, inv);
    #pragma unroll
    for (int i = 0; i < 3; i++) {
        int col = tid + i*256;
        h[(long)row*EE + col] = __float2half_rn((vals[i] - mu) * inv * g[col] + b[col]);
    }
}

// ================= fp16 tensor-core GEMM =================
// CTA BMxBN, (BN/128)*4 warps (2 x BN/64 grid), warp tile (BM/2)x64,
// BK=KB, 2-stage cp.async, ldmatrix. RS = KB + 8 halves.
template<int BM, int BN, int KB, bool BIAS, bool RELU, bool SPLITK,
         bool HALFOUT, bool LOSSACC>
__global__ void __launch_bounds__((BN/128)*128)
hgemm(const __half* __restrict__ A, const __half* __restrict__ B,
      const float* __restrict__ bias, void* __restrict__ Cv,
      int M, int N, int K, int Ksplit, int ldc, int Ncut,
      float* __restrict__ rowsum)
{
    constexpr int RS = KB + 8;
    constexpr int MT = BM / 32;
    constexpr int CPR = KB / 8;          // 16B chunks per row
    constexpr int TPB = (BN/128)*128;

    extern __shared__ __half smh[];
    const uint32_t sbase = smem_u32(smh);
    const uint32_t BOFF  = 2*BM*RS;      // B region follows 2-stage A region

    const int m0 = blockIdx.x * BM;
    const int n0 = blockIdx.y * BN;
    const int kbase = SPLITK ? blockIdx.z * Ksplit : 0;
    float*  Cf = (float*)Cv + (SPLITK ? (long)blockIdx.z * M * ldc : 0);
    __half* Ch = (__half*)Cv;

    const int tid = threadIdx.x;
    const int wid = tid >> 5, lane = tid & 31;
    const int wm = wid & 1, wn = wid >> 1;
    const int lrow = lane & 15, lchunk = (lane >> 4) * 8;

    float acc[MT][8][4];
    #pragma unroll
    for (int i = 0; i < MT; i++)
        #pragma unroll
        for (int j = 0; j < 8; j++)
            #pragma unroll
            for (int r = 0; r < 4; r++) acc[i][j][r] = 0.f;

    auto issue = [&](int st, int k0) {
        #pragma unroll
        for (int i = 0; i < BM*CPR/TPB; i++) {          // A tile
            int lin = tid + i * TPB;
            int r = lin / CPR, c = lin % CPR;
            CP_ASYNC16(sbase + (uint32_t)(st*BM*RS + r*RS + c*8)*2,
                       A + (long)(m0 + r)*K + kbase + k0 + c*8);
        }
        #pragma unroll
        for (int i = 0; i < BN*CPR/TPB; i++) {          // B tile
            int lin = tid + i * TPB;
            int r = lin / CPR, c = lin % CPR;
            CP_ASYNC16(sbase + (uint32_t)(BOFF + st*BN*RS + r*RS + c*8)*2,
                       B + (long)(n0 + r)*K + kbase + k0 + c*8);
        }
    };

    const int kIters = Ksplit / KB;
    issue(0, 0);  CP_COMMIT();

    int st = 0;
    for (int it = 0; it < kIters; it++) {
        if (it + 1 < kIters) {
            issue((it + 1) & 1, (it + 1) * KB);
            CP_COMMIT();
            CP_WAIT1();
        } else {
            CP_WAIT0();
        }
        __syncthreads();

        const uint32_t abase = sbase + (uint32_t)(st*BM*RS)*2;
        const uint32_t bbase = sbase + (uint32_t)(BOFF + st*BN*RS)*2;
        #pragma unroll
        for (int kk = 0; kk < KB; kk += 16) {
            uint32_t af[MT][4];
            #pragma unroll
            for (int mt = 0; mt < MT; mt++) {
                uint32_t addr = abase +
                    (uint32_t)((wm*(BM/2) + mt*16 + lrow)*RS + kk + lchunk)*2;
                LDMX4(af[mt][0], af[mt][1], af[mt][2], af[mt][3], addr);
            }
            uint32_t bf[4][4];
            #pragma unroll
            for (int nt16 = 0; nt16 < 4; nt16++) {
                uint32_t addr = bbase +
                    (uint32_t)((wn*64 + nt16*16 + lrow)*RS + kk + lchunk)*2;
                LDMX4(bf[nt16][0], bf[nt16][1], bf[nt16][2], bf[nt16][3], addr);
            }
            #pragma unroll
            for (int mt = 0; mt < MT; mt++)
                #pragma unroll
                for (int nt = 0; nt < 8; nt++) {
                    int g = nt >> 1, o = nt & 1;
                    mma_f16(acc[mt][nt], af[mt], bf[g][o], bf[g][2 + o]);
                }
        }
        __syncthreads();
        st ^= 1;
    }

    // ---- epilogue ----
    #pragma unroll
    for (int mt = 0; mt < MT; mt++) {
        int row = m0 + wm*(BM/2) + mt*16 + (lane >> 2);
        float ps[2] = {0.f, 0.f};
        #pragma unroll
        for (int nt = 0; nt < 8; nt++) {
            int gc = n0 + wn*64 + nt*8 + (lane & 3)*2;
            #pragma unroll
            for (int half = 0; half < 2; half++) {
                int rr = row + half*8;
                float v0 = acc[mt][nt][half*2 + 0];
                float v1 = acc[mt][nt][half*2 + 1];
                if (BIAS) {
                    if (LOSSACC) {
                        v0 += (gc     < Ncut) ? bias[gc]     : 0.f;
                        v1 += (gc + 1 < Ncut) ? bias[gc + 1] : 0.f;
                    } else {
                        v0 += bias[gc]; v1 += bias[gc + 1];
                    }
                }
                if (RELU) { v0 = fmaxf(v0, 0.f); v1 = fmaxf(v1, 0.f); }
                if (HALFOUT) {
                    *((__half2*)(Ch + (long)rr*ldc + gc)) = __floats2half2_rn(v0, v1);
                } else {
                    long off = (long)rr*ldc + gc;
                    if (gc < Ncut) {
                        Cf[off] = v0;
                        if (LOSSACC) ps[half] += exp_poly(v0);
                    }
                    if (gc + 1 < Ncut) {
                        Cf[off + 1] = v1;
                        if (LOSSACC) ps[half] += exp_poly(v1);
                    }
                }
            }
        }
        if (LOSSACC) {
            #pragma unroll
            for (int half = 0; half < 2; half++) {
                float p = ps[half];
                p += __shfl_xor_sync(0xFFFFFFFFu, p, 1);
                p += __shfl_xor_sync(0xFFFFFFFFu, p, 2);
                if ((lane & 3) == 0)
                    atomicAdd(&rowsum[row + half*8], p);
            }
        }
    }
}

// ================= attention: s-split, smem K/V, max-free softmax, 2-way s unroll ====
#define ATT_SMEM (2 * 128 * DD * 4)

__device__ __forceinline__ float att_dot(const float4* __restrict__ kr,
                                         const float4* __restrict__ q4)
{
    float d0 = 0.f, d1 = 0.f, d2 = 0.f, d3 = 0.f;
    #pragma unroll
    for (int i = 0; i < 16; i += 4) {
        float4 k0 = kr[i], k1 = kr[i+1], k2 = kr[i+2], k3 = kr[i+3];
        d0 += q4[i  ].x*k0.x + q4[i  ].y*k0.y + q4[i  ].z*k0.z + q4[i  ].w*k0.w;
        d1 += q4[i+1].x*k1.x + q4[i+1].y*k1.y + q4[i+1].z*k1.z + q4[i+1].w*k1.w;
        d2 += q4[i+2].x*k2.x + q4[i+2].y*k2.y + q4[i+2].z*k2.z + q4[i+2].w*k2.w;
        d3 += q4[i+3].x*k3.x + q4[i+3].y*k3.y + q4[i+3].z*k3.z + q4[i+3].w*k3.w;
    }
    return (d0 + d1) + (d2 + d3);
}

__global__ void __launch_bounds__(128)
attention_kernel(const __half* __restrict__ qkv, __half* __restrict__ o,
                 float* __restrict__ pacc, float* __restrict__ pl)
{
    const int bh = blockIdx.x;
    const int z  = blockIdx.y;
    const int b = bh / HH, h = bh % HH;
    const int tchunk = (z == 0) ? 0 : 1;
    const int schunk = (z == 2) ? 1 : 0;
    const int t = tchunk * 128 + threadIdx.x;
    const int srow0 = schunk * 128;

    extern __shared__ float smem[];
    float* Ks = smem;
    float* Vs = smem + 128 * DD;

    for (int i = threadIdx.x; i < 128 * 8; i += 128) {
        int row = i >> 3, c8 = i & 7;
        long grow = (long)(b*TT + srow0 + row) * E3;
        uint4 uk = ((const uint4*)(qkv + grow +   EE + h*DD))[c8];
        uint4 uv = ((const uint4*)(qkv + grow + 2*EE + h*DD))[c8];
        const __half2* hk = (const __half2*)&uk;
        const __half2* hv = (const __half2*)&uv;
        float* kd = Ks + row*DD + c8*8;
        float* vd = Vs + row*DD + c8*8;
        #pragma unroll
        for (int j = 0; j < 4; j++) {
            float2 fk = __half22float2(hk[j]);
            float2 fv = __half22float2(hv[j]);
            kd[j*2] = fk.x; kd[j*2+1] = fk.y;
            vd[j*2] = fv.x; vd[j*2+1] = fv.y;
        }
    }
    float4 q4[16];
    {
        const uint4* qp = (const uint4*)(qkv + (long)(b*TT + t)*E3 + h*DD);
        #pragma unroll
        for (int i = 0; i < 8; i++) {
            uint4 u = qp[i];
            const __half2* hp = (const __half2*)&u;
            float2 f0 = __half22float2(hp[0]);
            float2 f1 = __half22float2(hp[1]);
            float2 f2 = __half22float2(hp[2]);
            float2 f3 = __half22float2(hp[3]);
            q4[i*2]   = make_float4(f0.x, f0.y, f1.x, f1.y);
            q4[i*2+1] = make_float4(f2.x, f2.y, f3.x, f3.y);
        }
    }
    __syncthreads();

    const float scale = rsqrtf((float)EE);
    const int send = (z == 1) ? (srow0 + 127) : t;
    const int n = send - srow0 + 1;

    float l = 0.f;
    float4 acc[16];
    #pragma unroll
    for (int i = 0; i < 16; i++) acc[i] = make_float4(0.f, 0.f, 0.f, 0.f);

    int sloc = 0;
    for (; sloc + 2 <= n; sloc += 2) {
        const float4* kr0 = (const float4*)(Ks + sloc*DD);
        const float4* kr1 = (const float4*)(Ks + (sloc + 1)*DD);
        float e0 = __expf(att_dot(kr0, q4) * scale);
        float e1 = __expf(att_dot(kr1, q4) * scale);
        l += e0;
        l += e1;
        const float4* vr0 = (const float4*)(Vs + sloc*DD);
        const float4* vr1 = (const float4*)(Vs + (sloc + 1)*DD);
        #pragma unroll
        for (int i = 0; i < 16; i++) {
            float4 v0 = vr0[i];
            acc[i].x += e0 * v0.x; acc[i].y += e0 * v0.y;
            acc[i].z += e0 * v0.z; acc[i].w += e0 * v0.w;
        }
        #pragma unroll
        for (int i = 0; i < 16; i++) {
            float4 v1 = vr1[i];
            acc[i].x += e1 * v1.x; acc[i].y += e1 * v1.y;
            acc[i].z += e1 * v1.z; acc[i].w += e1 * v1.w;
        }
    }
    if (sloc < n) {
        const float4* kr = (const float4*)(Ks + sloc*DD);
        float e = __expf(att_dot(kr, q4) * scale);
        l += e;
        const float4* vr = (const float4*)(Vs + sloc*DD);
        #pragma unroll
        for (int i = 0; i < 16; i++) {
            float4 v = vr[i];
            acc[i].x += e * v.x; acc[i].y += e * v.y;
            acc[i].z += e * v.z; acc[i].w += e * v.w;
        }
    }

    if (z == 0) {
        float inv = 1.0f / l;
        __half2* orow = (__half2*)(o + (long)(b*TT + t)*EE + h*DD);
        #pragma unroll
        for (int i = 0; i < 16; i++) {
            orow[i*2]   = __floats2half2_rn(acc[i].x * inv, acc[i].y * inv);
            orow[i*2+1] = __floats2half2_rn(acc[i].z * inv, acc[i].w * inv);
        }
    } else {
        int prow = b*128 + (t - 128);
        float4* pa = (float4*)(pacc + (long)schunk*512*EE + (long)prow*EE + h*DD);
        #pragma unroll
        for (int i = 0; i < 16; i++) pa[i] = acc[i];
        pl[schunk*512*HH + prow*HH + h] = l;
    }
}

__global__ void __launch_bounds__(256)
att_combine(const float* __restrict__ pacc, const float* __restrict__ pl,
            __half* __restrict__ o)
{
    int prow = blockIdx.x;
    int b = prow >> 7, tt = prow & 127;
    long orow = (long)(b*TT + 128 + tt) * EE;
    __shared__ float inv[HH];
    if (threadIdx.x < HH)
        inv[threadIdx.x] = 1.0f /
            (pl[prow*HH + threadIdx.x] + pl[512*HH + prow*HH + threadIdx.x]);
    __syncthreads();
    #pragma unroll
    for (int i = 0; i < 3; i++) {
        int col = threadIdx.x + i*256;
        int h = col / DD;
        float v = pacc[(long)prow*EE + col] + pacc[512L*EE + (long)prow*EE + col];
        o[orow + col] = __float2half_rn(v * inv[h]);
    }
}

// ---------------- final loss ----------------
__global__ void __launch_bounds__(1024)
loss_final(const float* __restrict__ expsum,
           const float* __restrict__ logits,
           const int* __restrict__ tgt,
           float* __restrict__ out)
{
    __shared__ float red[1024];
    int row = threadIdx.x;
    float lt = logf(expsum[row]) - logits[(long)row*VV + tgt[row]];
    red[row] = lt;
    __syncthreads();
    for (int off = 512; off > 0; off >>= 1) {
        if (row < off) red[row] += red[row + off];
        __syncthreads();
    }
    if (row == 0) out[0] = red[0] * (1.0f / NT);
}

// ---------------- launch ----------------
extern "C" void kernel_launch(void* const* d_in, const int* in_sizes, int n_in,
                              void* d_out, int out_size)
{
    const int*   idx     = (const int*)  d_in[0];
    const int*   tgt     = (const int*)  d_in[1];
    const float* tok_emb = (const float*)d_in[2];
    const float* pos_emb = (const float*)d_in[3];
    const float* ln1_g   = (const float*)d_in[4];
    const float* ln1_b   = (const float*)d_in[5];
    const float* wq      = (const float*)d_in[6];
    const float* wk      = (const float*)d_in[7];
    const float* wv      = (const float*)d_in[8];
    const float* wo      = (const float*)d_in[9];
    const float* bo      = (const float*)d_in[10];
    const float* ln2_g   = (const float*)d_in[11];
    const float* ln2_b   = (const float*)d_in[12];
    const float* w1      = (const float*)d_in[13];
    const float* b1      = (const float*)d_in[14];
    const float* w2      = (const float*)d_in[15];
    const float* b2      = (const float*)d_in[16];
    const float* lnf_g   = (const float*)d_in[17];
    const float* lnf_b   = (const float*)d_in[18];
    const float* lm_w    = (const float*)d_in[19];
    const float* lm_b    = (const float*)d_in[20];
    float* out = (float*)d_out;

    float  *x, *part, *pl, *expsum;
    __half *h, *qkv, *o, *mlp, *wqkvT, *woT, *w1T, *w2T, *wlmT;
    cudaGetSymbolAddress((void**)&x,     g_x);
    cudaGetSymbolAddress((void**)&h,     g_h);
    cudaGetSymbolAddress((void**)&qkv,   g_qkv);
    cudaGetSymbolAddress((void**)&o,     g_o);
    cudaGetSymbolAddress((void**)&mlp,   g_mlp);
    cudaGetSymbolAddress((void**)&part,  g_part);
    cudaGetSymbolAddress((void**)&pl,    g_pl);
    cudaGetSymbolAddress((void**)&expsum,g_expsum);
    cudaGetSymbolAddress((void**)&wqkvT, g_wqkvT);
    cudaGetSymbolAddress((void**)&woT,   g_woT);
    cudaGetSymbolAddress((void**)&w1T,   g_w1T);
    cudaGetSymbolAddress((void**)&w2T,   g_w2T);
    cudaGetSymbolAddress((void**)&wlmT,  g_wlmT);

    const long BTV = (long)NT * VV;
    float* logits = out;

    // side stream for overlapped weight prep (created once; deterministic)
    static cudaStream_t s2 = nullptr;
    static cudaEvent_t evFork = nullptr, evJoinW = nullptr, evJoinLm = nullptr;
    if (!s2) {
        cudaStreamCreateWithFlags(&s2, cudaStreamNonBlocking);
        cudaEventCreateWithFlags(&evFork,   cudaEventDisableTiming);
        cudaEventCreateWithFlags(&evJoinW,  cudaEventDisableTiming);
        cudaEventCreateWithFlags(&evJoinLm, cudaEventDisableTiming);
    }

    auto kQkv  = hgemm<64, 128, 64, false,false,false, true,  false>;
    auto kSplit= hgemm<64, 128, 64, false,false,true,  false, false>;
    auto kMlp1 = hgemm<64, 128, 64, true, true, false, true,  false>;
    auto kLm   = hgemm<128,256, 64, true, false,false, false, true >;
    const size_t sm64 = (size_t)2 * (64 + 128) * 72 * 2;    // 55296
    const size_t smLm = (size_t)2 * (128 + 256) * 72 * 2;   // 110592
    cudaFuncSetAttribute(kQkv,  cudaFuncAttributeMaxDynamicSharedMemorySize, (int)sm64);
    cudaFuncSetAttribute(kSplit,cudaFuncAttributeMaxDynamicSharedMemorySize, (int)sm64);
    cudaFuncSetAttribute(kMlp1, cudaFuncAttributeMaxDynamicSharedMemorySize, (int)sm64);
    cudaFuncSetAttribute(kLm,   cudaFuncAttributeMaxDynamicSharedMemorySize, (int)smLm);
    cudaFuncSetAttribute(attention_kernel,
                         cudaFuncAttributeMaxDynamicSharedMemorySize, ATT_SMEM);

    // fork: wo/w1/w2 transposes + big lm_w transpose run on side stream
    dim3 tb(32, 8);
    cudaEventRecord(evFork, 0);
    cudaStreamWaitEvent(s2, evFork, 0);
    tr_half<<<dim3(EE/32, EE/32, LL), tb, 0, s2>>>(wo, woT,
        EE, EE, 1, (long)EE*EE, 0, (long)EE*EE, 0);
    tr_half<<<dim3(FF/32, EE/32, LL), tb, 0, s2>>>(w1, w1T,
        EE, FF, 1, (long)EE*FF, 0, (long)FF*EE, 0);
    tr_half<<<dim3(EE/32, FF/32, LL), tb, 0, s2>>>(w2, w2T,
        FF, EE, 1, (long)FF*EE, 0, (long)EE*FF, 0);
    cudaEventRecord(evJoinW, s2);
    tr_lm<<<dim3(VPAD/32, EE/64), 256, 0, s2>>>(lm_w, wlmT);
    cudaEventRecord(evJoinLm, s2);

    // ---- main stream: qkv weight transposes (needed first) + embed ----
    tr_half<<<dim3(DD/32, EE/32, LL*HH), tb>>>(wq, wqkvT,
        EE, DD, HH, (long)HH*EE*DD, (long)EE*DD, (long)E3*EE, (long)DD*EE);
    tr_half<<<dim3(DD/32, EE/32, LL*HH), tb>>>(wk, wqkvT + (long)EE*EE,
        EE, DD, HH, (long)HH*EE*DD, (long)EE*DD, (long)E3*EE, (long)DD*EE);
    tr_half<<<dim3(DD/32, EE/32, LL*HH), tb>>>(wv, wqkvT + 2L*EE*EE,
        EE, DD, HH, (long)HH*EE*DD, (long)EE*DD, (long)E3*EE, (long)DD*EE);

    zero_kernel<<<1, NT>>>(expsum);
    embed_ln_kernel<<<NT, 256>>>(idx, tok_emb, pos_emb, ln1_g, ln1_b, x, h);

    dim3 gQKV (NT/64, E3/128);             // 16 x 18
    dim3 gSpl (NT/64, EE/128, KSPL);       // 16 x 6 x 4
    dim3 gMlp1(NT/64, FF/128);             // 16 x 24
    dim3 gLm  (NT/128, VPAD/256);          // 8 x 392
    dim3 gAtt (BB*HH, 3);                  // 144 blocks

    for (int l = 0; l < LL; l++) {
        kQkv<<<gQKV, 128, sm64>>>(h, wqkvT + (long)l*E3*EE, nullptr, qkv,
                                  NT, E3, EE, EE, E3, E3, nullptr);

        attention_kernel<<<gAtt, 128, ATT_SMEM>>>(qkv, o, part, pl);
        att_combine<<<512, 256>>>(part, pl, o);

        if (l == 0) cudaStreamWaitEvent(0, evJoinW, 0);   // wo/w1/w2 ready
        kSplit<<<gSpl, 128, sm64>>>(o, woT + (long)l*EE*EE, nullptr, part,
                                    NT, EE, EE, EE/KSPL, EE, EE, nullptr);
        reduce_ln_kernel<<<NT, 256>>>(part, bo + (long)l*EE, x,
                                      ln2_g + (long)l*EE, ln2_b + (long)l*EE, h);

        kMlp1<<<gMlp1, 128, sm64>>>(h, w1T + (long)l*FF*EE, b1 + (long)l*FF, mlp,
                                    NT, FF, EE, EE, FF, FF, nullptr);

        kSplit<<<gSpl, 128, sm64>>>(mlp, w2T + (long)l*EE*FF, nullptr, part,
                                    NT, EE, FF, FF/KSPL, EE, EE, nullptr);
        const float* ng = (l + 1 < LL) ? ln1_g + (long)(l+1)*EE : lnf_g;
        const float* nb = (l + 1 < LL) ? ln1_b + (long)(l+1)*EE : lnf_b;
        reduce_ln_kernel<<<NT, 256>>>(part, b2 + (long)l*EE, x, ng, nb, h);
    }

    // join: wlmT must be ready before the LM head
    cudaStreamWaitEvent(0, evJoinLm, 0);
    kLm<<<gLm, 256, smLm>>>(h, wlmT, lm_b, logits, NT, VPAD, EE, EE, VV, VV, expsum);

    if ((long)out_size > BTV) {
        loss_final<<<1, 1024>>>(expsum, logits, tgt, out + BTV);
    }
}

// round 17
// speedup vs baseline: 1.0477x; 1.0477x over previous
#include <cuda_runtime.h>
#include <cuda_fp16.h>
#include <math.h>
#include <stdint.h>

// ---------------- problem constants ----------------
#define BB   4
#define TT   256
#define NT   (BB*TT)        // 1024 tokens
#define EE   768
#define E3   (3*EE)         // 2304
#define HH   12
#define DD   64
#define LL   6
#define VV   100277
#define VPAD 100352         // VV padded to multiple of 128
#define FF   (4*EE)         // 3072
#define KSPL 4              // split-K factor

// ---------------- scratch (device globals; no allocations) ----------------
__device__ float  g_x    [NT*EE];
__device__ __half g_h    [NT*EE];
__device__ __half g_qkv  [NT*E3];
__device__ __half g_o    [NT*EE];
__device__ __half g_mlp  [NT*FF];
__device__ float  g_part [KSPL*NT*EE];
__device__ float  g_pl   [2*512*HH];
__device__ float  g_expsum[NT];
__device__ __half g_wqkvT[(long)LL*E3*EE];
__device__ __half g_woT  [(long)LL*EE*EE];
__device__ __half g_w1T  [(long)LL*FF*EE];
__device__ __half g_w2T  [(long)LL*EE*FF];
__device__ __half g_wlmT [(long)VPAD*EE];

// ---------------- small helpers ----------------
__device__ __forceinline__ uint32_t smem_u32(const void* p) {
    uint32_t a;
    asm("{ .reg .u64 t; cvta.to.shared.u64 t, %1; cvt.u32.u64 %0, t; }" : "=r"(a) : "l"(p));
    return a;
}
#define CP_ASYNC16(dst, src) \
    asm volatile("cp.async.cg.shared.global [%0], [%1], 16;" :: "r"(dst), "l"(src))
#define CP_COMMIT() asm volatile("cp.async.commit_group;" ::: "memory")
#define CP_WAIT1()  asm volatile("cp.async.wait_group 1;" ::: "memory")
#define CP_WAIT0()  asm volatile("cp.async.wait_group 0;" ::: "memory")

#define LDMX4(r0, r1, r2, r3, addr) \
    asm volatile("ldmatrix.sync.aligned.m8n8.x4.shared.b16 {%0,%1,%2,%3}, [%4];" \
        : "=r"(r0), "=r"(r1), "=r"(r2), "=r"(r3) : "r"(addr))

__device__ __forceinline__ void mma_f16(float* c, const uint32_t* a,
                                        uint32_t b0, uint32_t b1) {
    asm volatile(
        "mma.sync.aligned.m16n8k16.row.col.f32.f16.f16.f32 "
        "{%0,%1,%2,%3}, {%4,%5,%6,%7}, {%8,%9}, {%0,%1,%2,%3};"
        : "+f"(c[0]), "+f"(c[1]), "+f"(c[2]), "+f"(c[3])
        : "r"(a[0]), "r"(a[1]), "r"(a[2]), "r"(a[3]), "r"(b0), "r"(b1));
}

// FMA-pipe exp: exp(x) = 2^(x*log2e), degree-6 poly, ~1e-8 rel.
__device__ __forceinline__ float exp_poly(float x) {
    float t = x * 1.4426950408889634f;
    float fi = floorf(t);
    float f = t - fi;
    float p = 1.535336188319500e-4f;
    p = p * f + 1.339887440266574e-3f;
    p = p * f + 9.618437357674640e-3f;
    p = p * f + 5.550332471162809e-2f;
    p = p * f + 2.402264791363012e-1f;
    p = p * f + 6.931472028550421e-1f;
    p = p * f + 1.0f;
    return p * __int_as_float(((int)fi + 127) << 23);
}

// ---------------- transpose + fp32->fp16 (small weights) ----------------
__global__ void tr_half(const float* __restrict__ src, __half* __restrict__ dst,
                        int K, int N, int zmod,
                        long zsl, long zsh, long zdl, long zdh)
{
    int z = blockIdx.z;
    int l = z / zmod, hh = z % zmod;
    src += (long)l*zsl + (long)hh*zsh;
    dst += (long)l*zdl + (long)hh*zdh;
    __shared__ float t[32][33];
    int n0 = blockIdx.x*32, k0 = blockIdx.y*32;
    #pragma unroll
    for (int j = 0; j < 4; j++) {
        int k = k0 + threadIdx.y + j*8, n = n0 + threadIdx.x;
        t[threadIdx.y + j*8][threadIdx.x] = src[(long)k*N + n];
    }
    __syncthreads();
    #pragma unroll
    for (int j = 0; j < 4; j++) {
        int n = n0 + threadIdx.y + j*8, k = k0 + threadIdx.x;
        dst[(long)n*K + k] = __float2half_rn(t[threadIdx.x][threadIdx.y + j*8]);
    }
}

// ---------------- fast lm_w transpose: [E][VV] fp32 -> [VPAD][E] half ----------------
__global__ void __launch_bounds__(256)
tr_lm(const float* __restrict__ src, __half* __restrict__ dst)
{
    __shared__ float t[64][33];
    int n0 = blockIdx.x*32, k0 = blockIdx.y*64;
    int tx = threadIdx.x & 31, ty = threadIdx.x >> 5;
    #pragma unroll
    for (int j = 0; j < 8; j++) {
        int k = ty + j*8;
        int n = n0 + tx;
        t[k][tx] = (n < VV) ? src[(long)(k0 + k)*VV + n] : 0.f;
    }
    __syncthreads();
    #pragma unroll
    for (int i = 0; i < 4; i++) {
        int idx = threadIdx.x + i*256;
        int n = idx >> 5;
        int c = idx & 31;
        __half2 hv = __floats2half2_rn(t[c*2][n], t[c*2+1][n]);
        *((__half2*)(dst + (long)(n0 + n)*EE + k0 + c*2)) = hv;
    }
}

__global__ void zero_kernel(float* p) { p[threadIdx.x] = 0.f; }

// ---------------- shared LN tail: warp-shuffle reduce of (s, s2) ----------------
__device__ __forceinline__ void ln_stats(float s, float s2, int tid,
                                         float& mu, float& inv)
{
    #pragma unroll
    for (int off = 16; off > 0; off >>= 1) {
        s  += __shfl_xor_sync(0xFFFFFFFFu, s,  off);
        s2 += __shfl_xor_sync(0xFFFFFFFFu, s2, off);
    }
    __shared__ float ws[8], ws2[8], smu, sinv;
    if ((tid & 31) == 0) { ws[tid >> 5] = s; ws2[tid >> 5] = s2; }
    __syncthreads();
    if (tid == 0) {
        float S = 0.f, S2 = 0.f;
        #pragma unroll
        for (int i = 0; i < 8; i++) { S += ws[i]; S2 += ws2[i]; }
        float m = S * (1.0f/EE);
        smu = m;
        sinv = rsqrtf(S2 * (1.0f/EE) - m*m + 1e-5f);
    }
    __syncthreads();
    mu = smu; inv = sinv;
}

// ---------------- fused embed + LN1(layer 0): h half ----------------
__global__ void embed_ln_kernel(const int* __restrict__ idx,
                                const float* __restrict__ tok,
                                const float* __restrict__ pos,
                                const float* __restrict__ g,
                                const float* __restrict__ b,
                                float* __restrict__ x,
                                __half* __restrict__ h)
{
    int row = blockIdx.x;
    int t   = row % TT;
    int token = idx[row];
    const float* tr = tok + (long)token * EE;
    const float* pr = pos + (long)t * EE;
    int tid = threadIdx.x;
    float vals[3];
    float s = 0.f, s2 = 0.f;
    #pragma unroll
    for (int i = 0; i < 3; i++) {
        int col = tid + i*256;
        float v = tr[col] + pr[col];
        x[(long)row*EE + col] = v;
        vals[i] = v; s += v; s2 += v*v;
    }
    float mu, inv;
    ln_stats(s, s2, tid, mu, inv);
    #pragma unroll
    for (int i = 0; i < 3; i++) {
        int col = tid + i*256;
        h[(long)row*EE + col] = __float2half_rn((vals[i] - mu) * inv * g[col] + b[col]);
    }
}

// ---------------- fused: x += sum(part)+bias; h = LN(x) half ----------------
__global__ void reduce_ln_kernel(const float* __restrict__ part,
                                 const float* __restrict__ bias,
                                 float* __restrict__ x,
                                 const float* __restrict__ g,
                                 const float* __restrict__ b,
                                 __half* __restrict__ h)
{
    int row = blockIdx.x;
    int tid = threadIdx.x;
    float vals[3];
    float s = 0.f, s2 = 0.f;
    #pragma unroll
    for (int i = 0; i < 3; i++) {
        int col = tid + i*256;
        float v = x[(long)row*EE + col] + bias[col];
        #pragma unroll
        for (int z = 0; z < KSPL; z++)
            v += part[((long)z*NT + row)*EE + col];
        x[(long)row*EE + col] = v;
        vals[i] = v; s += v; s2 += v*v;
    }
    float mu, inv;
    ln_stats(s, s2, tid, mu, inv);
    #pragma unroll
    for (int i = 0; i < 3; i++) {
        int col = tid + i*256;
        h[(long)row*EE + col] = __float2half_rn((vals[i] - mu) * inv * g[col] + b[col]);
    }
}

// ================= fp16 tensor-core GEMM =================
// CTA BMx128, 4 warps, warp tile (BM/2)x64, BK=KB, 2-stage cp.async, ldmatrix.
// RS = KB + 8 halves.
template<int BM, int KB, bool BIAS, bool RELU, bool SPLITK, bool HALFOUT, bool LOSSACC>
__global__ void __launch_bounds__(128)
hgemm(const __half* __restrict__ A, const __half* __restrict__ B,
      const float* __restrict__ bias, void* __restrict__ Cv,
      int M, int N, int K, int Ksplit, int ldc, int Ncut,
      float* __restrict__ rowsum)
{
    constexpr int RS = KB + 8;
    constexpr int MT = BM / 32;
    constexpr int CPR = KB / 8;          // 16B chunks per row

    extern __shared__ __half smh[];
    const uint32_t sbase = smem_u32(smh);
    const uint32_t BOFF  = 2*BM*RS;      // B region follows 2-stage A region

    const int m0 = blockIdx.x * BM;
    const int n0 = blockIdx.y * 128;
    const int kbase = SPLITK ? blockIdx.z * Ksplit : 0;
    float*  Cf = (float*)Cv + (SPLITK ? (long)blockIdx.z * M * ldc : 0);
    __half* Ch = (__half*)Cv;

    const int tid = threadIdx.x;
    const int wid = tid >> 5, lane = tid & 31;
    const int wm = wid & 1, wn = wid >> 1;
    const int lrow = lane & 15, lchunk = (lane >> 4) * 8;

    float acc[MT][8][4];
    #pragma unroll
    for (int i = 0; i < MT; i++)
        #pragma unroll
        for (int j = 0; j < 8; j++)
            #pragma unroll
            for (int r = 0; r < 4; r++) acc[i][j][r] = 0.f;

    auto issue = [&](int st, int k0) {
        #pragma unroll
        for (int i = 0; i < BM*CPR/128; i++) {          // A tile
            int lin = tid + i * 128;
            int r = lin / CPR, c = lin % CPR;
            CP_ASYNC16(sbase + (uint32_t)(st*BM*RS + r*RS + c*8)*2,
                       A + (long)(m0 + r)*K + kbase + k0 + c*8);
        }
        #pragma unroll
        for (int i = 0; i < 128*CPR/128; i++) {         // B tile (128 rows)
            int lin = tid + i * 128;
            int r = lin / CPR, c = lin % CPR;
            CP_ASYNC16(sbase + (uint32_t)(BOFF + st*128*RS + r*RS + c*8)*2,
                       B + (long)(n0 + r)*K + kbase + k0 + c*8);
        }
    };

    const int kIters = Ksplit / KB;
    issue(0, 0);  CP_COMMIT();

    int st = 0;
    for (int it = 0; it < kIters; it++) {
        if (it + 1 < kIters) {
            issue((it + 1) & 1, (it + 1) * KB);
            CP_COMMIT();
            CP_WAIT1();
        } else {
            CP_WAIT0();
        }
        __syncthreads();

        const uint32_t abase = sbase + (uint32_t)(st*BM*RS)*2;
        const uint32_t bbase = sbase + (uint32_t)(BOFF + st*128*RS)*2;
        #pragma unroll
        for (int kk = 0; kk < KB; kk += 16) {
            uint32_t af[MT][4];
            #pragma unroll
            for (int mt = 0; mt < MT; mt++) {
                uint32_t addr = abase +
                    (uint32_t)((wm*(BM/2) + mt*16 + lrow)*RS + kk + lchunk)*2;
                LDMX4(af[mt][0], af[mt][1], af[mt][2], af[mt][3], addr);
            }
            uint32_t bf[4][4];
            #pragma unroll
            for (int nt16 = 0; nt16 < 4; nt16++) {
                uint32_t addr = bbase +
                    (uint32_t)((wn*64 + nt16*16 + lrow)*RS + kk + lchunk)*2;
                LDMX4(bf[nt16][0], bf[nt16][1], bf[nt16][2], bf[nt16][3], addr);
            }
            #pragma unroll
            for (int mt = 0; mt < MT; mt++)
                #pragma unroll
                for (int nt = 0; nt < 8; nt++) {
                    int g = nt >> 1, o = nt & 1;
                    mma_f16(acc[mt][nt], af[mt], bf[g][o], bf[g][2 + o]);
                }
        }
        __syncthreads();
        st ^= 1;
    }

    // ---- epilogue ----
    #pragma unroll
    for (int mt = 0; mt < MT; mt++) {
        int row = m0 + wm*(BM/2) + mt*16 + (lane >> 2);
        float ps[2] = {0.f, 0.f};
        #pragma unroll
        for (int nt = 0; nt < 8; nt++) {
            int gc = n0 + wn*64 + nt*8 + (lane & 3)*2;
            #pragma unroll
            for (int half = 0; half < 2; half++) {
                int rr = row + half*8;
                float v0 = acc[mt][nt][half*2 + 0];
                float v1 = acc[mt][nt][half*2 + 1];
                if (BIAS) {
                    if (LOSSACC) {
                        v0 += (gc     < Ncut) ? bias[gc]     : 0.f;
                        v1 += (gc + 1 < Ncut) ? bias[gc + 1] : 0.f;
                    } else {
                        v0 += bias[gc]; v1 += bias[gc + 1];
                    }
                }
                if (RELU) { v0 = fmaxf(v0, 0.f); v1 = fmaxf(v1, 0.f); }
                if (HALFOUT) {
                    *((__half2*)(Ch + (long)rr*ldc + gc)) = __floats2half2_rn(v0, v1);
                } else {
                    long off = (long)rr*ldc + gc;
                    if (gc < Ncut) {
                        Cf[off] = v0;
                        if (LOSSACC) ps[half] += exp_poly(v0);
                    }
                    if (gc + 1 < Ncut) {
                        Cf[off + 1] = v1;
                        if (LOSSACC) ps[half] += exp_poly(v1);
                    }
                }
            }
        }
        if (LOSSACC) {
            #pragma unroll
            for (int half = 0; half < 2; half++) {
                float p = ps[half];
                p += __shfl_xor_sync(0xFFFFFFFFu, p, 1);
                p += __shfl_xor_sync(0xFFFFFFFFu, p, 2);
                if ((lane & 3) == 0)
                    atomicAdd(&rowsum[row + half*8], p);
            }
        }
    }
}

// ================= attention: s-split, smem K/V, max-free softmax, 2-way s unroll ====
#define ATT_SMEM (2 * 128 * DD * 4)

__device__ __forceinline__ float att_dot(const float4* __restrict__ kr,
                                         const float4* __restrict__ q4)
{
    float d0 = 0.f, d1 = 0.f, d2 = 0.f, d3 = 0.f;
    #pragma unroll
    for (int i = 0; i < 16; i += 4) {
        float4 k0 = kr[i], k1 = kr[i+1], k2 = kr[i+2], k3 = kr[i+3];
        d0 += q4[i  ].x*k0.x + q4[i  ].y*k0.y + q4[i  ].z*k0.z + q4[i  ].w*k0.w;
        d1 += q4[i+1].x*k1.x + q4[i+1].y*k1.y + q4[i+1].z*k1.z + q4[i+1].w*k1.w;
        d2 += q4[i+2].x*k2.x + q4[i+2].y*k2.y + q4[i+2].z*k2.z + q4[i+2].w*k2.w;
        d3 += q4[i+3].x*k3.x + q4[i+3].y*k3.y + q4[i+3].z*k3.z + q4[i+3].w*k3.w;
    }
    return (d0 + d1) + (d2 + d3);
}

__global__ void __launch_bounds__(128)
attention_kernel(const __half* __restrict__ qkv, __half* __restrict__ o,
                 float* __restrict__ pacc, float* __restrict__ pl)
{
    const int bh = blockIdx.x;
    const int z  = blockIdx.y;
    const int b = bh / HH, h = bh % HH;
    const int tchunk = (z == 0) ? 0 : 1;
    const int schunk = (z == 2) ? 1 : 0;
    const int t = tchunk * 128 + threadIdx.x;
    const int srow0 = schunk * 128;

    extern __shared__ float smem[];
    float* Ks = smem;
    float* Vs = smem + 128 * DD;

    for (int i = threadIdx.x; i < 128 * 8; i += 128) {
        int row = i >> 3, c8 = i & 7;
        long grow = (long)(b*TT + srow0 + row) * E3;
        uint4 uk = ((const uint4*)(qkv + grow +   EE + h*DD))[c8];
        uint4 uv = ((const uint4*)(qkv + grow + 2*EE + h*DD))[c8];
        const __half2* hk = (const __half2*)&uk;
        const __half2* hv = (const __half2*)&uv;
        float* kd = Ks + row*DD + c8*8;
        float* vd = Vs + row*DD + c8*8;
        #pragma unroll
        for (int j = 0; j < 4; j++) {
            float2 fk = __half22float2(hk[j]);
            float2 fv = __half22float2(hv[j]);
            kd[j*2] = fk.x; kd[j*2+1] = fk.y;
            vd[j*2] = fv.x; vd[j*2+1] = fv.y;
        }
    }
    float4 q4[16];
    {
        const uint4* qp = (const uint4*)(qkv + (long)(b*TT + t)*E3 + h*DD);
        #pragma unroll
        for (int i = 0; i < 8; i++) {
            uint4 u = qp[i];
            const __half2* hp = (const __half2*)&u;
            float2 f0 = __half22float2(hp[0]);
            float2 f1 = __half22float2(hp[1]);
            float2 f2 = __half22float2(hp[2]);
            float2 f3 = __half22float2(hp[3]);
            q4[i*2]   = make_float4(f0.x, f0.y, f1.x, f1.y);
            q4[i*2+1] = make_float4(f2.x, f2.y, f3.x, f3.y);
        }
    }
    __syncthreads();

    const float scale = rsqrtf((float)EE);
    const int send = (z == 1) ? (srow0 + 127) : t;
    const int n = send - srow0 + 1;

    float l = 0.f;
    float4 acc[16];
    #pragma unroll
    for (int i = 0; i < 16; i++) acc[i] = make_float4(0.f, 0.f, 0.f, 0.f);

    int sloc = 0;
    for (; sloc + 2 <= n; sloc += 2) {
        const float4* kr0 = (const float4*)(Ks + sloc*DD);
        const float4* kr1 = (const float4*)(Ks + (sloc + 1)*DD);
        float e0 = __expf(att_dot(kr0, q4) * scale);
        float e1 = __expf(att_dot(kr1, q4) * scale);
        l += e0;
        l += e1;
        const float4* vr0 = (const float4*)(Vs + sloc*DD);
        const float4* vr1 = (const float4*)(Vs + (sloc + 1)*DD);
        #pragma unroll
        for (int i = 0; i < 16; i++) {
            float4 v0 = vr0[i];
            acc[i].x += e0 * v0.x; acc[i].y += e0 * v0.y;
            acc[i].z += e0 * v0.z; acc[i].w += e0 * v0.w;
        }
        #pragma unroll
        for (int i = 0; i < 16; i++) {
            float4 v1 = vr1[i];
            acc[i].x += e1 * v1.x; acc[i].y += e1 * v1.y;
            acc[i].z += e1 * v1.z; acc[i].w += e1 * v1.w;
        }
    }
    if (sloc < n) {
        const float4* kr = (const float4*)(Ks + sloc*DD);
        float e = __expf(att_dot(kr, q4) * scale);
        l += e;
        const float4* vr = (const float4*)(Vs + sloc*DD);
        #pragma unroll
        for (int i = 0; i < 16; i++) {
            float4 v = vr[i];
            acc[i].x += e * v.x; acc[i].y += e * v.y;
            acc[i].z += e * v.z; acc[i].w += e * v.w;
        }
    }

    if (z == 0) {
        float inv = 1.0f / l;
        __half2* orow = (__half2*)(o + (long)(b*TT + t)*EE + h*DD);
        #pragma unroll
        for (int i = 0; i < 16; i++) {
            orow[i*2]   = __floats2half2_rn(acc[i].x * inv, acc[i].y * inv);
            orow[i*2+1] = __floats2half2_rn(acc[i].z * inv, acc[i].w * inv);
        }
    } else {
        int prow = b*128 + (t - 128);
        float4* pa = (float4*)(pacc + (long)schunk*512*EE + (long)prow*EE + h*DD);
        #pragma unroll
        for (int i = 0; i < 16; i++) pa[i] = acc[i];
        pl[schunk*512*HH + prow*HH + h] = l;
    }
}

__global__ void __launch_bounds__(256)
att_combine(const float* __restrict__ pacc, const float* __restrict__ pl,
            __half* __restrict__ o)
{
    int prow = blockIdx.x;
    int b = prow >> 7, tt = prow & 127;
    long orow = (long)(b*TT + 128 + tt) * EE;
    __shared__ float inv[HH];
    if (threadIdx.x < HH)
        inv[threadIdx.x] = 1.0f /
            (pl[prow*HH + threadIdx.x] + pl[512*HH + prow*HH + threadIdx.x]);
    __syncthreads();
    #pragma unroll
    for (int i = 0; i < 3; i++) {
        int col = threadIdx.x + i*256;
        int h = col / DD;
        float v = pacc[(long)prow*EE + col] + pacc[512L*EE + (long)prow*EE + col];
        o[orow + col] = __float2half_rn(v * inv[h]);
    }
}

// ---------------- final loss ----------------
__global__ void __launch_bounds__(1024)
loss_final(const float* __restrict__ expsum,
           const float* __restrict__ logits,
           const int* __restrict__ tgt,
           float* __restrict__ out)
{
    __shared__ float red[1024];
    int row = threadIdx.x;
    float lt = logf(expsum[row]) - logits[(long)row*VV + tgt[row]];
    red[row] = lt;
    __syncthreads();
    for (int off = 512; off > 0; off >>= 1) {
        if (row < off) red[row] += red[row + off];
        __syncthreads();
    }
    if (row == 0) out[0] = red[0] * (1.0f / NT);
}

// ---------------- launch ----------------
extern "C" void kernel_launch(void* const* d_in, const int* in_sizes, int n_in,
                              void* d_out, int out_size)
{
    const int*   idx     = (const int*)  d_in[0];
    const int*   tgt     = (const int*)  d_in[1];
    const float* tok_emb = (const float*)d_in[2];
    const float* pos_emb = (const float*)d_in[3];
    const float* ln1_g   = (const float*)d_in[4];
    const float* ln1_b   = (const float*)d_in[5];
    const float* wq      = (const float*)d_in[6];
    const float* wk      = (const float*)d_in[7];
    const float* wv      = (const float*)d_in[8];
    const float* wo      = (const float*)d_in[9];
    const float* bo      = (const float*)d_in[10];
    const float* ln2_g   = (const float*)d_in[11];
    const float* ln2_b   = (const float*)d_in[12];
    const float* w1      = (const float*)d_in[13];
    const float* b1      = (const float*)d_in[14];
    const float* w2      = (const float*)d_in[15];
    const float* b2      = (const float*)d_in[16];
    const float* lnf_g   = (const float*)d_in[17];
    const float* lnf_b   = (const float*)d_in[18];
    const float* lm_w    = (const float*)d_in[19];
    const float* lm_b    = (const float*)d_in[20];
    float* out = (float*)d_out;

    float  *x, *part, *pl, *expsum;
    __half *h, *qkv, *o, *mlp, *wqkvT, *woT, *w1T, *w2T, *wlmT;
    cudaGetSymbolAddress((void**)&x,     g_x);
    cudaGetSymbolAddress((void**)&h,     g_h);
    cudaGetSymbolAddress((void**)&qkv,   g_qkv);
    cudaGetSymbolAddress((void**)&o,     g_o);
    cudaGetSymbolAddress((void**)&mlp,   g_mlp);
    cudaGetSymbolAddress((void**)&part,  g_part);
    cudaGetSymbolAddress((void**)&pl,    g_pl);
    cudaGetSymbolAddress((void**)&expsum,g_expsum);
    cudaGetSymbolAddress((void**)&wqkvT, g_wqkvT);
    cudaGetSymbolAddress((void**)&woT,   g_woT);
    cudaGetSymbolAddress((void**)&w1T,   g_w1T);
    cudaGetSymbolAddress((void**)&w2T,   g_w2T);
    cudaGetSymbolAddress((void**)&wlmT,  g_wlmT);

    const long BTV = (long)NT * VV;
    float* logits = out;

    // side stream for overlapped weight prep (created once; deterministic)
    static cudaStream_t s2 = nullptr;
    static cudaEvent_t evFork = nullptr, evJoinW = nullptr, evJoinLm = nullptr;
    if (!s2) {
        cudaStreamCreateWithFlags(&s2, cudaStreamNonBlocking);
        cudaEventCreateWithFlags(&evFork,   cudaEventDisableTiming);
        cudaEventCreateWithFlags(&evJoinW,  cudaEventDisableTiming);
        cudaEventCreateWithFlags(&evJoinLm, cudaEventDisableTiming);
    }

    auto kQkv  = hgemm<64, 64, false,false,false, true,  false>;
    auto kSplit= hgemm<64, 64, false,false,true,  false, false>;
    auto kMlp1 = hgemm<64, 64, true, true, false, true,  false>;
    auto kLm   = hgemm<128,64, true, false,false, false, true >;
    const size_t sm64  = (size_t)2 * (64 + 128) * 72 * 2;   // 55296
    const size_t sm128 = (size_t)2 * (128 + 128) * 72 * 2;  // 73728
    cudaFuncSetAttribute(kQkv,  cudaFuncAttributeMaxDynamicSharedMemorySize, (int)sm64);
    cudaFuncSetAttribute(kSplit,cudaFuncAttributeMaxDynamicSharedMemorySize, (int)sm64);
    cudaFuncSetAttribute(kMlp1, cudaFuncAttributeMaxDynamicSharedMemorySize, (int)sm64);
    cudaFuncSetAttribute(kLm,   cudaFuncAttributeMaxDynamicSharedMemorySize, (int)sm128);
    cudaFuncSetAttribute(attention_kernel,
                         cudaFuncAttributeMaxDynamicSharedMemorySize, ATT_SMEM);

    // fork: wo/w1/w2 transposes + big lm_w transpose run on side stream
    dim3 tb(32, 8);
    cudaEventRecord(evFork, 0);
    cudaStreamWaitEvent(s2, evFork, 0);
    tr_half<<<dim3(EE/32, EE/32, LL), tb, 0, s2>>>(wo, woT,
        EE, EE, 1, (long)EE*EE, 0, (long)EE*EE, 0);
    tr_half<<<dim3(FF/32, EE/32, LL), tb, 0, s2>>>(w1, w1T,
        EE, FF, 1, (long)EE*FF, 0, (long)FF*EE, 0);
    tr_half<<<dim3(EE/32, FF/32, LL), tb, 0, s2>>>(w2, w2T,
        FF, EE, 1, (long)FF*EE, 0, (long)EE*FF, 0);
    cudaEventRecord(evJoinW, s2);
    tr_lm<<<dim3(VPAD/32, EE/64), 256, 0, s2>>>(lm_w, wlmT);
    cudaEventRecord(evJoinLm, s2);

    // ---- main stream: qkv weight transposes (needed first) + embed ----
    tr_half<<<dim3(DD/32, EE/32, LL*HH), tb>>>(wq, wqkvT,
        EE, DD, HH, (long)HH*EE*DD, (long)EE*DD, (long)E3*EE, (long)DD*EE);
    tr_half<<<dim3(DD/32, EE/32, LL*HH), tb>>>(wk, wqkvT + (long)EE*EE,
        EE, DD, HH, (long)HH*EE*DD, (long)EE*DD, (long)E3*EE, (long)DD*EE);
    tr_half<<<dim3(DD/32, EE/32, LL*HH), tb>>>(wv, wqkvT + 2L*EE*EE,
        EE, DD, HH, (long)HH*EE*DD, (long)EE*DD, (long)E3*EE, (long)DD*EE);

    zero_kernel<<<1, NT>>>(expsum);
    embed_ln_kernel<<<NT, 256>>>(idx, tok_emb, pos_emb, ln1_g, ln1_b, x, h);

    dim3 gQKV (NT/64, E3/128);             // 16 x 18
    dim3 gSpl (NT/64, EE/128, KSPL);       // 16 x 6 x 4
    dim3 gMlp1(NT/64, FF/128);             // 16 x 24
    dim3 gLm  (NT/128, VPAD/128);          // 8 x 784
    dim3 gAtt (BB*HH, 3);                  // 144 blocks

    for (int l = 0; l < LL; l++) {
        kQkv<<<gQKV, 128, sm64>>>(h, wqkvT + (long)l*E3*EE, nullptr, qkv,
                                  NT, E3, EE, EE, E3, E3, nullptr);

        attention_kernel<<<gAtt, 128, ATT_SMEM>>>(qkv, o, part, pl);
        att_combine<<<512, 256>>>(part, pl, o);

        if (l == 0) cudaStreamWaitEvent(0, evJoinW, 0);   // wo/w1/w2 ready
        kSplit<<<gSpl, 128, sm64>>>(o, woT + (long)l*EE*EE, nullptr, part,
                                    NT, EE, EE, EE/KSPL, EE, EE, nullptr);
        reduce_ln_kernel<<<NT, 256>>>(part, bo + (long)l*EE, x,
                                      ln2_g + (long)l*EE, ln2_b + (long)l*EE, h);

        kMlp1<<<gMlp1, 128, sm64>>>(h, w1T + (long)l*FF*EE, b1 + (long)l*FF, mlp,
                                    NT, FF, EE, EE, FF, FF, nullptr);

        kSplit<<<gSpl, 128, sm64>>>(mlp, w2T + (long)l*EE*FF, nullptr, part,
                                    NT, EE, FF, FF/KSPL, EE, EE, nullptr);
        const float* ng = (l + 1 < LL) ? ln1_g + (long)(l+1)*EE : lnf_g;
        const float* nb = (l + 1 < LL) ? ln1_b + (long)(l+1)*EE : lnf_b;
        reduce_ln_kernel<<<NT, 256>>>(part, b2 + (long)l*EE, x, ng, nb, h);
    }

    // join: wlmT must be ready before the LM head
    cudaStreamWaitEvent(0, evJoinLm, 0);
    kLm<<<gLm, 128, sm128>>>(h, wlmT, lm_b, logits, NT, VPAD, EE, EE, VV, VV, expsum);

    if ((long)out_size > BTV) {
        loss_final<<<1, 1024>>>(expsum, logits, tgt, out + BTV);
    }
}